// round 3
// baseline (speedup 1.0000x reference)
#include <cuda_runtime.h>
#include <cuda_bf16.h>

// SemiLoss focal loss (gamma=6), single fused kernel:
//   logits : [N, K, P] f32
//   seg    : [N, P]    int64 or int32 (runtime-sniffed)
//   label  : [N]       same int dtype
//   loss = -sum_{n: label[n]!=0} sum_p (1-exp(lp))^6 * lp / count(label!=0)
//   out  = [loss, 0, loss, 0, ...]
//
// Completion protocol: every block atomically accumulates into g_total,
// threadfence, then atomicInc on g_done (which wraps back to 0 on the last
// block — self-resetting). The last block computes the final loss, writes
// d_out, and resets g_total, keeping the kernel deterministic across
// CUDA-graph replays.

__device__ double       g_total = 0.0;
__device__ unsigned int g_done  = 0u;

__device__ __forceinline__ float focal_term(float lp)
{
    float pt = expf(lp);
    float u  = 1.0f - pt;
    float u2 = u * u;
    return u2 * u2 * u2 * lp;   // positive form; negated at the end
}

__global__ __launch_bounds__(256)
void semiloss_fused(const float* __restrict__ logits,
                    const void*  __restrict__ seg,
                    const void*  __restrict__ label,
                    int N, int K, int P,
                    unsigned int totalBlocks,
                    float* __restrict__ out, int out_size)
{
    const int n   = blockIdx.y;
    const int tid = threadIdx.x;

    // ---- dtype sniff: int64 (LE) => every odd 32-bit word of seg is 0 ----
    __shared__ int s_is64;
    if (tid < 32) {
        const int* w = (const int*)seg;
        unsigned b = __ballot_sync(0xffffffffu, w[2 * tid + 1] == 0);
        if (tid == 0) s_is64 = (b == 0xffffffffu) ? 1 : 0;
    }
    __syncthreads();
    const int is64 = s_is64;

    // ---- row active? (uniform broadcast load) ----
    long long lv;
    if (is64) lv = ((const long long*)label)[n];
    else      lv = (long long)((const int*)label)[n];
    const bool active = (lv != 0);

    // ---- gather-reduce: 8 pixels per thread ----
    double acc = 0.0;
    if (active) {
        const float* base = logits + (size_t)n * (size_t)K * (size_t)P;
        int p0 = (blockIdx.x * blockDim.x + tid) * 8;

        if (p0 + 8 <= P) {
            int c[8];
            if (is64) {
                const longlong2* s =
                    (const longlong2*)((const char*)seg + ((size_t)n * P + p0) * 8);
                #pragma unroll
                for (int i = 0; i < 4; ++i) {
                    longlong2 a = s[i];
                    c[2 * i]     = (int)a.x;
                    c[2 * i + 1] = (int)a.y;
                }
            } else {
                const int4* s =
                    (const int4*)((const char*)seg + ((size_t)n * P + p0) * 4);
                int4 a = s[0], b = s[1];
                c[0] = a.x; c[1] = a.y; c[2] = a.z; c[3] = a.w;
                c[4] = b.x; c[5] = b.y; c[6] = b.z; c[7] = b.w;
            }
            float l[8];
            #pragma unroll
            for (int i = 0; i < 8; ++i)
                l[i] = __ldg(base + (size_t)c[i] * P + p0 + i);
            #pragma unroll
            for (int i = 0; i < 8; ++i)
                acc += (double)focal_term(l[i]);
        } else {
            for (int p = p0; p < P; ++p) {
                int cc;
                if (is64) cc = (int)((const long long*)seg)[(size_t)n * P + p];
                else      cc = ((const int*)seg)[(size_t)n * P + p];
                acc += (double)focal_term(__ldg(base + (size_t)cc * P + p));
            }
        }
    }

    // ---- block reduction (double) ----
    for (int off = 16; off > 0; off >>= 1)
        acc += __shfl_down_sync(0xffffffffu, acc, off);
    __shared__ double s_part[8];
    const int lane = tid & 31, wid = tid >> 5;
    if (lane == 0) s_part[wid] = acc;
    __syncthreads();

    __shared__ int s_islast;
    if (tid == 0) {
        double v = 0.0;
        #pragma unroll
        for (int w = 0; w < 8; ++w) v += s_part[w];
        if (v != 0.0) atomicAdd(&g_total, v);
        __threadfence();
        // atomicInc wraps to 0 when old == totalBlocks-1 -> self-resetting
        unsigned old = atomicInc(&g_done, totalBlocks - 1u);
        s_islast = (old == totalBlocks - 1u) ? 1 : 0;
    }
    __syncthreads();

    // ---- last block: finalize ----
    if (s_islast) {
        __shared__ float s_loss;
        if (tid == 0) {
            // count nonzero labels (N is tiny)
            int cnt = 0;
            if (is64) {
                const long long* lb = (const long long*)label;
                for (int i = 0; i < N; ++i) cnt += (lb[i] != 0);
            } else {
                const int* lb = (const int*)label;
                for (int i = 0; i < N; ++i) cnt += (lb[i] != 0);
            }
            double tot = *((volatile double*)&g_total);
            s_loss = (float)(-tot / (double)cnt);
            g_total = 0.0;           // reset for next replay (g_done wrapped)
            __threadfence();
        }
        __syncthreads();
        float loss = s_loss;
        for (int i = tid; i < out_size; i += blockDim.x)
            out[i] = (i == 0 || i == 2) ? loss : 0.0f;
    }
}

extern "C" void kernel_launch(void* const* d_in, const int* in_sizes, int n_in,
                              void* d_out, int out_size)
{
    const float* logits = (const float*)d_in[0];
    const void*  seg    = d_in[1];
    const void*  label  = d_in[2];

    int N = in_sizes[2];                 // B*S
    int P = in_sizes[1] / N;             // H*W
    int K = in_sizes[0] / in_sizes[1];   // classes

    const int THREADS = 256;
    const int PX_PER_BLOCK = THREADS * 8;
    int blocksPerRow = (P + PX_PER_BLOCK - 1) / PX_PER_BLOCK;
    dim3 grid(blocksPerRow, N);
    unsigned int totalBlocks = (unsigned int)blocksPerRow * (unsigned int)N;

    semiloss_fused<<<grid, THREADS>>>(logits, seg, label, N, K, P,
                                      totalBlocks, (float*)d_out, out_size);
}

// round 4
// speedup vs baseline: 1.2149x; 1.2149x over previous
#include <cuda_runtime.h>
#include <cuda_bf16.h>

// SemiLoss focal loss (gamma=6), single fused kernel with work compaction:
//   logits : [N, K, P] f32
//   seg    : [N, P]    int64 or int32 (runtime-sniffed)
//   label  : [N]       same int dtype
//   loss = -sum_{n: label[n]!=0} sum_p (1-exp(lp))^6 * lp / count(label!=0)
//   out  = [loss, 0, loss, 0, ...]
//
// Work mapping: work item w in [0, cnt*chunksPerRow) covers chunk (w % cpr)
// of the (w / cpr)-th ACTIVE row. blockIdx.x == w. Blocks with
// blockIdx.x >= cnt*cpr have no gather work. Because working items are the
// lowest block indices, the RR block->SM scheduler spreads them uniformly
// across SMs regardless of which rows are active.
//
// Completion: atomicAdd into g_total, threadfence, atomicInc(g_done) wrapping
// at totalBlocks (self-resetting); last block finalizes out and resets
// g_total — deterministic across CUDA-graph replays.

#define CHUNK_PX   2048            // pixels per work item (256 thr * 8 px)
#define MAXROWS    1024

__device__ double       g_total = 0.0;
__device__ unsigned int g_done  = 0u;

__device__ __forceinline__ float focal_term(float lp)
{
    float pt = expf(lp);
    float u  = 1.0f - pt;
    float u2 = u * u;
    return u2 * u2 * u2 * lp;   // positive form; negated at the end
}

__global__ __launch_bounds__(256)
void semiloss_fused(const float* __restrict__ logits,
                    const void*  __restrict__ seg,
                    const void*  __restrict__ label,
                    int N, int K, int P, int chunksPerRow,
                    unsigned int totalBlocks,
                    float* __restrict__ out, int out_size)
{
    const int tid = threadIdx.x;

    // ---- dtype sniff: int64 (LE) => every odd 32-bit word of seg is 0 ----
    __shared__ int s_is64;
    if (tid < 32) {
        const int* w = (const int*)seg;
        unsigned b = __ballot_sync(0xffffffffu, w[2 * tid + 1] == 0);
        if (tid == 0) s_is64 = (b == 0xffffffffu) ? 1 : 0;
    }
    __syncthreads();
    const int is64 = s_is64;

    // ---- load label activity flags (parallel, one transaction) ----
    __shared__ unsigned char s_act[MAXROWS];
    __shared__ int s_row;     // resolved row for this block (-1: no work)
    __shared__ int s_cnt;     // total active rows
    for (int i = tid; i < N; i += blockDim.x) {
        long long lv;
        if (is64) lv = ((const long long*)label)[i];
        else      lv = (long long)((const int*)label)[i];
        s_act[i] = (lv != 0) ? 1 : 0;
    }
    __syncthreads();
    if (tid == 0) {
        int q = blockIdx.x / chunksPerRow;   // which active row ordinal
        int cnt = 0, row = -1;
        for (int i = 0; i < N; ++i) {
            if (s_act[i]) {
                if (cnt == q) row = i;
                ++cnt;
            }
        }
        s_row = row;
        s_cnt = cnt;
    }
    __syncthreads();
    const int row = s_row;

    // ---- gather-reduce: 8 pixels per thread, warp-coalesced (stride 256) ----
    double acc = 0.0;
    if (row >= 0) {
        const int chunk = blockIdx.x % chunksPerRow;
        const int p0    = chunk * CHUNK_PX + tid;
        const float* base = logits + (size_t)row * (size_t)K * (size_t)P;

        if (p0 + 7 * 256 < P) {
            int c[8];
            if (is64) {
                const long long* s = (const long long*)seg + (size_t)row * P;
                #pragma unroll
                for (int i = 0; i < 8; ++i) c[i] = (int)s[p0 + 256 * i];
            } else {
                const int* s = (const int*)seg + (size_t)row * P;
                #pragma unroll
                for (int i = 0; i < 8; ++i) c[i] = s[p0 + 256 * i];
            }
            float l[8];
            #pragma unroll
            for (int i = 0; i < 8; ++i)
                l[i] = __ldg(base + (size_t)c[i] * P + p0 + 256 * i);
            #pragma unroll
            for (int i = 0; i < 8; ++i)
                acc += (double)focal_term(l[i]);
        } else {
            for (int i = 0; i < 8; ++i) {
                int p = p0 + 256 * i;
                if (p >= P) break;
                int cc;
                if (is64) cc = (int)((const long long*)seg)[(size_t)row * P + p];
                else      cc = ((const int*)seg)[(size_t)row * P + p];
                acc += (double)focal_term(__ldg(base + (size_t)cc * P + p));
            }
        }
    }

    // ---- block reduction (double) ----
    for (int off = 16; off > 0; off >>= 1)
        acc += __shfl_down_sync(0xffffffffu, acc, off);
    __shared__ double s_part[8];
    const int lane = tid & 31, wid = tid >> 5;
    if (lane == 0) s_part[wid] = acc;
    __syncthreads();

    __shared__ int s_islast;
    if (tid == 0) {
        double v = 0.0;
        #pragma unroll
        for (int w = 0; w < 8; ++w) v += s_part[w];
        if (v != 0.0) atomicAdd(&g_total, v);
        __threadfence();
        unsigned old = atomicInc(&g_done, totalBlocks - 1u);
        s_islast = (old == totalBlocks - 1u) ? 1 : 0;
    }
    __syncthreads();

    // ---- last block: finalize ----
    if (s_islast) {
        __shared__ float s_loss;
        if (tid == 0) {
            double tot = *((volatile double*)&g_total);
            s_loss = (float)(-tot / (double)s_cnt);
            g_total = 0.0;           // reset for next replay (g_done wrapped)
            __threadfence();
        }
        __syncthreads();
        float loss = s_loss;
        for (int i = tid; i < out_size; i += blockDim.x)
            out[i] = (i == 0 || i == 2) ? loss : 0.0f;
    }
}

extern "C" void kernel_launch(void* const* d_in, const int* in_sizes, int n_in,
                              void* d_out, int out_size)
{
    const float* logits = (const float*)d_in[0];
    const void*  seg    = d_in[1];
    const void*  label  = d_in[2];

    int N = in_sizes[2];                 // B*S
    int P = in_sizes[1] / N;             // H*W
    int K = in_sizes[0] / in_sizes[1];   // classes

    const int THREADS = 256;
    int chunksPerRow = (P + CHUNK_PX - 1) / CHUNK_PX;
    unsigned int totalBlocks = (unsigned int)N * (unsigned int)chunksPerRow;

    semiloss_fused<<<totalBlocks, THREADS>>>(logits, seg, label,
                                             N, K, P, chunksPerRow,
                                             totalBlocks,
                                             (float*)d_out, out_size);
}